// round 9
// baseline (speedup 1.0000x reference)
#include <cuda_runtime.h>

// ---------------------------------------------------------------------------
// Micromagnetic LLG solver (RK4, 5-pt exchange laplacian, SOT, demag-z).
// Round 8:
//   - NT 512 -> 1024 (32 warps/CTA, occ 25% -> 50%), NQ 4 -> 2: same total
//     work, 2x warps per scheduler to hide LDS/sync/global latency
//   - otherwise round-7 structure: 2 concurrent replicas, halo-fused RK4
//     (4 stages / grid sync), 32x32 interior + halo 4, shrinking stage cone,
//     float4 smem ping-pong stencil, central-counter barrier
// ---------------------------------------------------------------------------

#define NXg 256
#define NYg 256
#define NCELL (NXg * NYg)
#define TSTEPS 256
#define NSRC 3
#define NPROBE 5
#define RELAX_STEPS 100

#define NB 128          // 2 replicas x 64 tiles, 1 CTA/SM, single wave
#define NT 1024
#define HALO 4
#define EXT 40          // 32 + 2*4
#define MAXC (EXT * EXT)  // 1600
#define NQ 2
#define SMEM_BYTES (2 * MAXC * (int)sizeof(float4))   // 51200

// [replica][parity][cell]
__device__ float4 g_fld[2][2][NCELL];
__device__ unsigned int g_cnt[2];
__device__ volatile unsigned int g_gen[2];

__global__ void reset_kernel() {
    if (threadIdx.x < 2) {
        g_cnt[threadIdx.x] = 0u;
        g_gen[threadIdx.x] = 0u;
    }
}

// Replica-local grid barrier: 64 arrivals on one counter, one-word gen poll
// by thread 0 only.
__device__ __forceinline__ void gbar(int r, unsigned int v) {
    __syncthreads();
    if (threadIdx.x == 0) {
        __threadfence();
        if (atomicAdd(&g_cnt[r], 1u) == 63u) {
            g_cnt[r] = 0u;
            __threadfence();
            g_gen[r] = v;
        } else {
            while (g_gen[r] < v) { }
        }
    }
    __syncthreads();
}

__global__ void __launch_bounds__(NT, 1)
mm_solver_kernel(const float* __restrict__ sigarr,   // [2, TSTEPS, NSRC]
                 const float* __restrict__ Bext,     // [1,3,NX,NY]
                 const float* __restrict__ msat,
                 const int*   __restrict__ srcp,     // [NSRC,2]
                 const int*   __restrict__ probep,   // [NPROBE,2]
                 const int*   __restrict__ fb,
                 float*       __restrict__ out)      // [2, TSTEPS, NPROBE]
{
    extern __shared__ float4 sb4[];    // [2][MAXC] ping-pong

    const int tid = threadIdx.x;
    const int r  = blockIdx.x >> 6;       // replica = signal index
    const int tb = blockIdx.x & 63;
    const int tx = tb >> 3, ty = tb & 7;
    const int x0 = tx * 32, y0 = ty * 32;

    const float Msat = msat[0];
    const int finalb = fb[0];
    const float ce = (float)(2.0 * 3.5e-12 / ((double)Msat * (5e-8 * 5e-8)));
    const float cd = (float)(-(1.2566370614359172e-06) * (double)Msat);
    const float h  = (float)(175950000000.0 * 5e-12);
    const float h6 = (float)((175950000000.0 * 5e-12) / 6.0);
    const float C_SOT = 1.0e-4f;

    // meta bits: [0:3)=limp1 (stage st computed iff st < limp1), bit3=valid,
    //            bit4=interior, [8:16)=src idx+1, [16:24)=probe idx+1
    int meta[NQ], nbN[NQ], nbS[NQ], nbW[NQ], nbE[NQ], ig[NQ];
    float Bcx[NQ], Bcy[NQ], Bcz[NQ];
    float m0x[NQ], m0y[NQ], m0z[NQ];
    float mrelz[NQ];

#pragma unroll
    for (int q = 0; q < NQ; ++q) {
        int c  = tid + q * NT;
        int cc = (c < MAXC) ? c : 0;
        int sx = cc / EXT, sy = cc % EXT;
        int gx = x0 - HALO + sx, gy = y0 - HALO + sy;
        bool valid = (c < MAXC) && gx >= 0 && gx < NXg && gy >= 0 && gy < NYg;
        bool inter = valid && gx >= x0 && gx < x0 + 32 && gy >= y0 && gy < y0 + 32;
        // ring distance d = max outward distance from the 32x32 interior
        int dxn = (sx < HALO) ? (HALO - sx) : (sx >= HALO + 32 ? sx - (HALO + 31) : 0);
        int dyn = (sy < HALO) ? (HALO - sy) : (sy >= HALO + 32 ? sy - (HALO + 31) : 0);
        int d = dxn > dyn ? dxn : dyn;
        int limp1 = valid ? (4 - d) : 0;           // stages computed: st < limp1
        if (limp1 < 0) limp1 = 0;
        // neighbor clamp-to-self at physical edges (pad mode='edge'); ext-edge
        // clamps only ever feed rings outside the dependence cone
        nbN[q] = (sx > 0       && gx > 0      ) ? cc - EXT : cc;
        nbS[q] = (sx < EXT - 1 && gx < NXg - 1) ? cc + EXT : cc;
        nbW[q] = (sy > 0       && gy > 0      ) ? cc - 1   : cc;
        nbE[q] = (sy < EXT - 1 && gy < NYg - 1) ? cc + 1   : cc;
        int gxc = gx < 0 ? 0 : (gx > NXg - 1 ? NXg - 1 : gx);
        int gyc = gy < 0 ? 0 : (gy > NYg - 1 ? NYg - 1 : gy);
        int ign = gxc * NYg + gyc;
        ig[q] = ign;
        Bcx[q] = Bext[ign];
        Bcy[q] = Bext[NCELL + ign];
        Bcz[q] = Bext[2 * NCELL + ign];
        int sj = 0, pj = 0;
        if (valid) {
#pragma unroll
            for (int k2 = 0; k2 < NSRC; ++k2)
                if (srcp[2 * k2] == gx && srcp[2 * k2 + 1] == gy) sj = k2 + 1;
            if (inter) {
#pragma unroll
                for (int k2 = 0; k2 < NPROBE; ++k2)
                    if (probep[2 * k2] == gx && probep[2 * k2 + 1] == gy) pj = k2 + 1;
            }
        }
        meta[q] = limp1 | (valid ? 8 : 0) | (inter ? 16 : 0) | (sj << 8) | (pj << 16);
        m0x[q] = 0.0f; m0y[q] = 1.0f; m0z[q] = 0.0f;
        mrelz[q] = 0.0f;
        if (inter) g_fld[r][0][ign] = make_float4(0.0f, 1.0f, 0.0f, 0.0f);
    }

    unsigned int gv = 0;
    int cur = 0;
    gbar(r, ++gv);

    float sx_[NQ], sy_[NQ], sz_[NQ], ax_[NQ], ay_[NQ], az_[NQ], sg[NQ];

    // ---- unified step loop: 100 relax + 256 run ----
#pragma unroll 1
    for (int i = 0; i < RELAX_STEPS + TSTEPS; ++i) {
        const bool run = (i >= RELAX_STEPS);
        const int  t   = i - RELAX_STEPS;
        const float alpha = run ? 0.01f : 0.5f;
        const float inv   = run ? (1.0f / (1.0f + 0.01f * 0.01f))
                                : (1.0f / (1.0f + 0.5f * 0.5f));
        const float* sgb = sigarr + (r * TSTEPS + (run ? t : 0)) * NSRC;

        // load phase: interior from regs, halo from L2; fill stage buffer 0
#pragma unroll
        for (int q = 0; q < NQ; ++q) {
            int mt = meta[q];
            sg[q] = 0.0f;
            ax_[q] = ay_[q] = az_[q] = 0.0f;
            if (mt & 8) {
                float vx, vy, vz;
                if (mt & 16) { vx = m0x[q]; vy = m0y[q]; vz = m0z[q]; }
                else {
                    float4 f = __ldcg(&g_fld[r][cur][ig[q]]);
                    vx = f.x; vy = f.y; vz = f.z;
                }
                m0x[q] = vx; m0y[q] = vy; m0z[q] = vz;
                sx_[q] = vx; sy_[q] = vy; sz_[q] = vz;
                sb4[tid + q * NT] = make_float4(vx, vy, vz, 0.0f);
                int sj = (mt >> 8) & 255;
                if (sj && run) sg[q] = __ldg(sgb + sj - 1);
            }
        }
        __syncthreads();

        // 4 RK4 stages in shared memory; active set shrinks by 1 ring/stage
        int p = 0;
        const float cst[3] = {0.5f, 0.5f, 1.0f};
        const float wst[4] = {1.0f, 2.0f, 2.0f, 1.0f};
#pragma unroll
        for (int st = 0; st < 4; ++st) {
            const float4* __restrict__ rb = sb4 + p * MAXC;
            float4* __restrict__ wb = sb4 + (p ^ 1) * MAXC;
#pragma unroll
            for (int q = 0; q < NQ; ++q) {
                if (st < (meta[q] & 7)) {
                    float4 nN = rb[nbN[q]];
                    float4 nS = rb[nbS[q]];
                    float4 nW = rb[nbW[q]];
                    float4 nE = rb[nbE[q]];

                    float lx = nN.x + nS.x + nW.x + nE.x - 4.0f * sx_[q];
                    float ly = nN.y + nS.y + nW.y + nE.y - 4.0f * sy_[q];
                    float lz = nN.z + nS.z + nW.z + nE.z - 4.0f * sz_[q];

                    float Bx = Bcx[q] + ce * lx;
                    float By = Bcy[q] + ce * ly;
                    float Bz = Bcz[q] + ce * lz + cd * sz_[q] + sg[q];

                    float cx = sy_[q] * Bz - sz_[q] * By;
                    float cy = sz_[q] * Bx - sx_[q] * Bz;
                    float cz = sx_[q] * By - sy_[q] * Bx;
                    float dx = sy_[q] * cz - sz_[q] * cy;
                    float dy = sz_[q] * cx - sx_[q] * cz;
                    float dz = sx_[q] * cy - sy_[q] * cx;
                    float ox = sy_[q] * sx_[q];
                    float oy = -(sz_[q] * sz_[q] + sx_[q] * sx_[q]);
                    float oz = sy_[q] * sz_[q];

                    float kx = -inv * (cx + alpha * dx) + C_SOT * ox;
                    float ky = -inv * (cy + alpha * dy) + C_SOT * oy;
                    float kz = -inv * (cz + alpha * dz) + C_SOT * oz;

                    ax_[q] += wst[st] * kx;
                    ay_[q] += wst[st] * ky;
                    az_[q] += wst[st] * kz;

                    if (st < 3) {
                        float cf = cst[st] * h;
                        sx_[q] = m0x[q] + cf * kx;
                        sy_[q] = m0y[q] + cf * ky;
                        sz_[q] = m0z[q] + cf * kz;
                        wb[tid + q * NT] = make_float4(sx_[q], sy_[q], sz_[q], 0.0f);
                    } else {
                        sx_[q] = m0x[q] + h6 * ax_[q];
                        sy_[q] = m0y[q] + h6 * ay_[q];
                        sz_[q] = m0z[q] + h6 * az_[q];
                    }
                }
            }
            if (st < 3) { __syncthreads(); p ^= 1; }
        }

        // store interior, capture relaxed z, emit probes
#pragma unroll
        for (int q = 0; q < NQ; ++q) {
            int mt = meta[q];
            if (mt & 16) {
                m0x[q] = sx_[q]; m0y[q] = sy_[q]; m0z[q] = sz_[q];
                g_fld[r][cur ^ 1][ig[q]] = make_float4(sx_[q], sy_[q], sz_[q], 0.0f);
                if (i == RELAX_STEPS - 1) mrelz[q] = sz_[q];
                int pj = (mt >> 16) & 255;
                if (pj && run) {
                    float v = finalb ? (sz_[q] - mrelz[q]) * Msat : sz_[q];
                    out[(r * TSTEPS + t) * NPROBE + pj - 1] = v;
                }
            }
        }
        cur ^= 1;
        gbar(r, ++gv);
    }
}

extern "C" void kernel_launch(void* const* d_in, const int* in_sizes, int n_in,
                              void* d_out, int out_size) {
    const float* list_signal = (const float*)d_in[0];
    const float* B_ext       = (const float*)d_in[1];
    const float* Msat        = (const float*)d_in[2];
    const int*   src_pos     = (const int*)d_in[3];
    const int*   probe_pos   = (const int*)d_in[4];
    const int*   final_board = (const int*)d_in[5];
    float*       out         = (float*)d_out;

    cudaFuncSetAttribute(mm_solver_kernel,
                         cudaFuncAttributeMaxDynamicSharedMemorySize, SMEM_BYTES);
    reset_kernel<<<1, 32>>>();
    mm_solver_kernel<<<NB, NT, SMEM_BYTES>>>(list_signal, B_ext, Msat, src_pos,
                                             probe_pos, final_board, out);
}